// round 12
// baseline (speedup 1.0000x reference)
#include <cuda_runtime.h>
#include <cuda_bf16.h>
#include <math.h>
#include <stdint.h>

// ---------------- problem constants ----------------
#define Bv   8
#define Mv   256
#define Ev   128
#define Kv   16
#define Hv   1024
#define Av   256
#define Rv   1024
#define RMSv 512
#define NEGV (-1e25f)
#define MROWS (Bv*Ev*Kv)   // 16384
#define NBE   (Bv*Ev)      // 1024
#define NMENT (Bv*Mv)      // 2048 distinct mention rows

// ---------------- scratch (static device globals) ----------------
__device__ float g_mv[NMENT * Av];     // per-mention V projection
__device__ float g_mu[NMENT * Av];     // per-mention U projection
__device__ float g_gate[NMENT];        // per-mention gate logit
__device__ float g_er[NBE * Hv];       // pooled entity reprs
__device__ float g_swT[Hv * Rv];       // swT[h,r] = (Wr @ RM^T)[h,r]
__device__ float g_W2[Hv * RMSv];      // W2[h,m]  = (swT @ RM)[h,m]
__device__ float g_Wc[Hv * Hv];        // Wcomb[o,h] = Wo1 + Wo2@W2^T + d br^T
__device__ float g_rmT[RMSv * Rv];     // RM^T
__device__ float g_q[RMSv];            // colsum(RM)
__device__ float g_d[Hv];              // d[o] = Wo2[o,:].q

// ---------------- helpers ----------------
__device__ __forceinline__ uint32_t smem_u32(const void* p) {
    uint32_t a;
    asm("{ .reg .u64 t; cvta.to.shared.u64 t, %1; cvt.u32.u64 %0, t; }" : "=r"(a) : "l"(p));
    return a;
}
__device__ __forceinline__ uint32_t pack_bf16x2(float x, float y) {
    __nv_bfloat162 h = __floats2bfloat162_rn(x, y);
    return *(uint32_t*)&h;
}
__device__ __forceinline__ float bf16_round(float x) {
    return __bfloat162float(__float2bfloat16(x));
}

#define LDMATRIX_X4(r0, r1, r2, r3, addr) \
    asm volatile("ldmatrix.sync.aligned.m8n8.x4.shared.b16 {%0,%1,%2,%3}, [%4];" \
        : "=r"(r0), "=r"(r1), "=r"(r2), "=r"(r3) : "r"(addr))

#define MMA_BF16(c, a, b) \
    asm volatile("mma.sync.aligned.m16n8k16.row.col.f32.bf16.bf16.f32 " \
        "{%0,%1,%2,%3}, {%4,%5,%6,%7}, {%8,%9}, {%0,%1,%2,%3};" \
        : "+f"((c)[0]), "+f"((c)[1]), "+f"((c)[2]), "+f"((c)[3]) \
        : "r"((a)[0]), "r"((a)[1]), "r"((a)[2]), "r"((a)[3]), "r"((b)[0]), "r"((b)[1]))

// ---------------------------------------------------------------------------
// Multi-job NT GEMM, bf16x3 fp32 emulation, double-buffered smem,
// register-staged prefetch. C[M,N] = A[M,K] * B[N,K]^T (+bias[n]) (+addM) (+u v^T)
// BM=64, BN=128, BK=32, 256 threads (8 warps, 2x4). 1-D grid, job dispatch.
// ---------------------------------------------------------------------------
struct GJob {
    const float *A, *B;
    float *C;
    const float *bias;   // per-col, nullable
    const float *addM;   // addend matrix [row,col], nullable
    const float *r1u;    // rank-1 u[row], nullable (with r1v)
    const float *r1v;    // rank-1 v[col]
    int lda, ldb, ldc, ldadd, Kdim, nb, nblk;
};

#define SMEM_BYTES 61440
// per-buffer: A = 2 splits x 64 x 40, B = 2 splits x 128 x 40 (bf16)
#define SA_OFF(buf, sp, row) ((buf)*15360 + (sp)*2560 + (row)*40)
#define SB_OFF(buf, sp, row) ((buf)*15360 + 5120 + (sp)*5120 + (row)*40)

__global__ __launch_bounds__(256)
void gemm3_kernel(GJob j0, GJob j1, GJob j2)
{
    extern __shared__ __nv_bfloat16 smw[];
    constexpr int AIT = 2, BIT = 4, NT = 4;

    int bid = blockIdx.x;
    GJob j = j0;
    if (bid >= j0.nblk) {
        bid -= j0.nblk; j = j1;
        if (bid >= j1.nblk) { bid -= j1.nblk; j = j2; }
    }

    const int tid  = threadIdx.x;
    const int wid  = tid >> 5;
    const int lane = tid & 31;
    const int warp_m = wid & 1;
    const int warp_n = wid >> 1;
    const int m0 = (bid / j.nb) * 64;
    const int n0 = (bid % j.nb) * 128;

    const int srow = tid >> 3;            // 0..31
    const int sc4  = (tid & 7) << 2;      // 0,4,...,28

    const float* aBase = j.A + (size_t)(m0 + srow) * j.lda + sc4;
    const float* bBase = j.B + (size_t)(n0 + srow) * j.ldb + sc4;

    float4 ra[AIT], rb[BIT];
    #pragma unroll
    for (int i = 0; i < AIT; i++) ra[i] = *(const float4*)(aBase + (size_t)(i * 32) * j.lda);
    #pragma unroll
    for (int i = 0; i < BIT; i++) rb[i] = *(const float4*)(bBase + (size_t)(i * 32) * j.ldb);

    float cfr[2][NT][4];
    #pragma unroll
    for (int mt = 0; mt < 2; mt++)
        #pragma unroll
        for (int nt = 0; nt < NT; nt++)
            #pragma unroll
            for (int q = 0; q < 4; q++) cfr[mt][nt][q] = 0.0f;

    const int nCh = j.Kdim >> 5;
    for (int ch = 0; ch < nCh; ch++) {
        const int buf = ch & 1;
        // ---- convert staged regs -> smem (hi/lo bf16) ----
        #pragma unroll
        for (int i = 0; i < AIT; i++) {
            float4 v = ra[i];
            int row = i * 32 + srow;
            float hx = bf16_round(v.x), hy = bf16_round(v.y);
            float hz = bf16_round(v.z), hw = bf16_round(v.w);
            uint2 hi, lo;
            hi.x = pack_bf16x2(hx, hy);         hi.y = pack_bf16x2(hz, hw);
            lo.x = pack_bf16x2(v.x-hx, v.y-hy); lo.y = pack_bf16x2(v.z-hz, v.w-hw);
            *(uint2*)(smw + SA_OFF(buf, 0, row) + sc4) = hi;
            *(uint2*)(smw + SA_OFF(buf, 1, row) + sc4) = lo;
        }
        #pragma unroll
        for (int i = 0; i < BIT; i++) {
            float4 v = rb[i];
            int row = i * 32 + srow;
            float hx = bf16_round(v.x), hy = bf16_round(v.y);
            float hz = bf16_round(v.z), hw = bf16_round(v.w);
            uint2 hi, lo;
            hi.x = pack_bf16x2(hx, hy);         hi.y = pack_bf16x2(hz, hw);
            lo.x = pack_bf16x2(v.x-hx, v.y-hy); lo.y = pack_bf16x2(v.z-hz, v.w-hw);
            *(uint2*)(smw + SB_OFF(buf, 0, row) + sc4) = hi;
            *(uint2*)(smw + SB_OFF(buf, 1, row) + sc4) = lo;
        }
        __syncthreads();   // single barrier per chunk (double buffered)

        // ---- prefetch next chunk (overlaps MMA) ----
        if (ch + 1 < nCh) {
            int koff = (ch + 1) << 5;
            #pragma unroll
            for (int i = 0; i < AIT; i++) ra[i] = *(const float4*)(aBase + (size_t)(i * 32) * j.lda + koff);
            #pragma unroll
            for (int i = 0; i < BIT; i++) rb[i] = *(const float4*)(bBase + (size_t)(i * 32) * j.ldb + koff);
        }

        // ---- MMA: per k-step 3 split products, fragment reuse ----
        #pragma unroll
        for (int ks = 0; ks < 2; ks++) {
            const int acol = ks * 16 + ((lane >> 4) << 3);
            const int arow = warp_m * 32 + (lane & 15);
            const int bcol = ks * 16 + (((lane >> 3) & 1) << 3);
            const int brow = warp_n * 32 + (lane & 7) + ((lane >> 4) << 3);

            uint32_t afH[2][4];
            #pragma unroll
            for (int mt = 0; mt < 2; mt++)
                LDMATRIX_X4(afH[mt][0], afH[mt][1], afH[mt][2], afH[mt][3],
                            smem_u32(smw + SA_OFF(buf, 0, arow + mt * 16) + acol));
            uint32_t bfH[NT][2];
            #pragma unroll
            for (int np = 0; np < NT / 2; np++) {
                uint32_t r0, r1, r2, r3;
                LDMATRIX_X4(r0, r1, r2, r3,
                            smem_u32(smw + SB_OFF(buf, 0, brow + np * 16) + bcol));
                bfH[np*2][0] = r0;   bfH[np*2][1] = r1;
                bfH[np*2+1][0] = r2; bfH[np*2+1][1] = r3;
            }
            #pragma unroll
            for (int mt = 0; mt < 2; mt++)
                #pragma unroll
                for (int nt = 0; nt < NT; nt++) MMA_BF16(cfr[mt][nt], afH[mt], bfH[nt]);
            {
                uint32_t bfL[NT][2];
                #pragma unroll
                for (int np = 0; np < NT / 2; np++) {
                    uint32_t r0, r1, r2, r3;
                    LDMATRIX_X4(r0, r1, r2, r3,
                                smem_u32(smw + SB_OFF(buf, 1, brow + np * 16) + bcol));
                    bfL[np*2][0] = r0;   bfL[np*2][1] = r1;
                    bfL[np*2+1][0] = r2; bfL[np*2+1][1] = r3;
                }
                #pragma unroll
                for (int mt = 0; mt < 2; mt++)
                    #pragma unroll
                    for (int nt = 0; nt < NT; nt++) MMA_BF16(cfr[mt][nt], afH[mt], bfL[nt]);
            }
            {
                uint32_t afL[2][4];
                #pragma unroll
                for (int mt = 0; mt < 2; mt++)
                    LDMATRIX_X4(afL[mt][0], afL[mt][1], afL[mt][2], afL[mt][3],
                                smem_u32(smw + SA_OFF(buf, 1, arow + mt * 16) + acol));
                #pragma unroll
                for (int mt = 0; mt < 2; mt++)
                    #pragma unroll
                    for (int nt = 0; nt < NT; nt++) MMA_BF16(cfr[mt][nt], afL[mt], bfH[nt]);
            }
        }
        __syncthreads();   // protect buf reuse two chunks later
    }

    // ---- epilogue ----
    const int g = lane >> 2;
    const int t = lane & 3;
    #pragma unroll
    for (int mt = 0; mt < 2; mt++) {
        #pragma unroll
        for (int nt = 0; nt < NT; nt++) {
            int row = m0 + warp_m * 32 + mt * 16 + g;
            int col = n0 + warp_n * 32 + nt * 8 + t * 2;
            float v0 = cfr[mt][nt][0], v1 = cfr[mt][nt][1];
            float v2 = cfr[mt][nt][2], v3 = cfr[mt][nt][3];
            if (j.addM) {
                const float* q0 = &j.addM[(size_t)row * j.ldadd + col];
                const float* q1 = &j.addM[(size_t)(row + 8) * j.ldadd + col];
                v0 += q0[0]; v1 += q0[1]; v2 += q1[0]; v3 += q1[1];
            }
            if (j.r1u) {
                float u0 = j.r1u[row], u1 = j.r1u[row + 8];
                float w0 = j.r1v[col], w1 = j.r1v[col + 1];
                v0 += u0 * w0; v1 += u0 * w1; v2 += u1 * w0; v3 += u1 * w1;
            }
            if (j.bias) {
                float b0 = j.bias[col], b1 = j.bias[col + 1];
                v0 += b0; v1 += b1; v2 += b0; v3 += b1;
            }
            float* p0 = &j.C[(size_t)row * j.ldc + col];
            float* p1 = &j.C[(size_t)(row + 8) * j.ldc + col];
            *(float2*)p0 = make_float2(v0, v1);
            *(float2*)p1 = make_float2(v2, v3);
        }
    }
}

// ---------------- per-mention gate: tanh(mv+bv)*sigmoid(mu+bu) . Wa ----------------
__global__ __launch_bounds__(256)
void gate_kernel(const float* __restrict__ bv, const float* __restrict__ bu,
                 const float* __restrict__ Wa)
{
    int r = blockIdx.x * 8 + (threadIdx.x >> 5);
    int lane = threadIdx.x & 31;
    const float* pv = g_mv + (size_t)r * Av;
    const float* pu = g_mu + (size_t)r * Av;
    float s = 0.0f;
    #pragma unroll
    for (int jj = 0; jj < 8; jj++) {
        int a = lane + jj * 32;
        float tv = tanhf(pv[a] + bv[a]);
        float su = 1.0f / (1.0f + expf(-(pu[a] + bu[a])));
        s += tv * su * Wa[a];
    }
    #pragma unroll
    for (int o = 16; o > 0; o >>= 1) s += __shfl_xor_sync(0xFFFFFFFF, s, o);
    if (lane == 0) g_gate[r] = s;
}

// ---------------- masked softmax over K + weighted pooling ----------------
__global__ __launch_bounds__(256)
void softmax_pool_kernel(const float* __restrict__ mention,
                         const int*   __restrict__ entities,
                         const int*   __restrict__ masks)
{
    const int be = blockIdx.x;
    const int b  = be / Ev;
    __shared__ float w[Kv];
    __shared__ int   idx[Kv];
    const int tid = threadIdx.x;
    if (tid < Kv) {
        int r = be * Kv + tid;
        int m = entities[r];
        idx[tid] = m;
        w[tid]   = masks[r] ? g_gate[b * Mv + m] : NEGV;
    }
    __syncthreads();
    if (tid == 0) {
        float mx = w[0];
        #pragma unroll
        for (int k = 1; k < Kv; k++) mx = fmaxf(mx, w[k]);
        float s = 0.0f;
        #pragma unroll
        for (int k = 0; k < Kv; k++) { float e = expf(w[k] - mx); w[k] = e; s += e; }
        float inv = 1.0f / s;
        #pragma unroll
        for (int k = 0; k < Kv; k++) w[k] *= inv;
    }
    __syncthreads();
    float ww[Kv]; int ii[Kv];
    #pragma unroll
    for (int k = 0; k < Kv; k++) { ww[k] = w[k]; ii[k] = idx[k]; }
    const float* base = mention + (size_t)b * Mv * Hv;
    for (int h = tid; h < Hv; h += 256) {
        float acc = 0.0f;
        #pragma unroll
        for (int k = 0; k < Kv; k++)
            acc += ww[k] * base[(size_t)ii[k] * Hv + h];
        g_er[(size_t)be * Hv + h] = acc;
    }
}

// ---------------- transpose relation_memory: g_rmT[m,r] = RM[r,m] ----------------
__global__ void transpose_rm_kernel(const float* __restrict__ RM)
{
    __shared__ float tile[32][33];
    int tx = threadIdx.x, ty = threadIdx.y;
    int n0 = blockIdx.x * 32, k0 = blockIdx.y * 32;
    #pragma unroll
    for (int jj = 0; jj < 32; jj += 8)
        tile[ty + jj][tx] = RM[(size_t)(k0 + ty + jj) * RMSv + n0 + tx];
    __syncthreads();
    #pragma unroll
    for (int jj = 0; jj < 32; jj += 8)
        g_rmT[(size_t)(n0 + ty + jj) * Rv + k0 + tx] = tile[tx][ty + jj];
}

// ---------------- q = colsum(RM) ----------------
__global__ __launch_bounds__(128)
void colsum_kernel(const float* __restrict__ RM)
{
    int col = blockIdx.x * 128 + threadIdx.x;   // 4 blocks x 128 = 512
    float s = 0.0f;
    for (int r = 0; r < Rv; r++) s += RM[(size_t)r * RMSv + col];
    g_q[col] = s;
}

// ---------------- d[o] = Wo2[o,:] . q ----------------
__global__ __launch_bounds__(256)
void dvec_kernel(const float* __restrict__ Wo2, int ldw)
{
    int o = blockIdx.x * 8 + (threadIdx.x >> 5);
    int lane = threadIdx.x & 31;
    const float* row = Wo2 + (size_t)o * ldw;
    float s = 0.0f;
    #pragma unroll
    for (int jj = 0; jj < RMSv / 32; jj++) s += row[lane + jj * 32] * g_q[lane + jj * 32];
    #pragma unroll
    for (int off = 16; off > 0; off >>= 1) s += __shfl_xor_sync(0xFFFFFFFF, s, off);
    if (lane == 0) g_d[o] = s;
}

// ---------------- launch ----------------
extern "C" void kernel_launch(void* const* d_in, const int* in_sizes, int n_in,
                              void* d_out, int out_size)
{
    const float* mention  = (const float*)d_in[0];
    const int*   entities = (const int*)  d_in[1];
    const int*   masks    = (const int*)  d_in[2];
    const float* RM       = (const float*)d_in[3];
    const float* Wv       = (const float*)d_in[4];
    const float* bv       = (const float*)d_in[5];
    const float* Wu       = (const float*)d_in[6];
    const float* bu       = (const float*)d_in[7];
    const float* Wa       = (const float*)d_in[8];
    // d_in[9] = ba : additive constant inside softmax -> no-op
    const float* Wr       = (const float*)d_in[10];
    const float* br       = (const float*)d_in[11];
    const float* Wo       = (const float*)d_in[12];
    const float* bo       = (const float*)d_in[13];
    float* out = (float*)d_out;

    cudaFuncSetAttribute(gemm3_kernel, cudaFuncAttributeMaxDynamicSharedMemorySize, SMEM_BYTES);

    float *p_mv, *p_mu, *p_er, *p_swT, *p_W2, *p_Wc, *p_rmT, *p_d;
    cudaGetSymbolAddress((void**)&p_mv,  g_mv);
    cudaGetSymbolAddress((void**)&p_mu,  g_mu);
    cudaGetSymbolAddress((void**)&p_er,  g_er);
    cudaGetSymbolAddress((void**)&p_swT, g_swT);
    cudaGetSymbolAddress((void**)&p_W2,  g_W2);
    cudaGetSymbolAddress((void**)&p_Wc,  g_Wc);
    cudaGetSymbolAddress((void**)&p_rmT, g_rmT);
    cudaGetSymbolAddress((void**)&p_d,   g_d);

    GJob Z = {};   // zero job (nblk = 0)

    // 1. transpose RM -> rmT [512, 1024]; q = colsum(RM)
    { dim3 g(RMSv / 32, Rv / 32), b(32, 8); transpose_rm_kernel<<<g, b>>>(RM); }
    colsum_kernel<<<RMSv / 128, 128>>>(RM);

    // 2. fused launch: mv = mention@Wv^T, mu = mention@Wu^T, swT = Wr@RM^T
    {
        GJob jv = { mention, Wv, p_mv, nullptr, nullptr, nullptr, nullptr,
                    Hv, Hv, Av, 0, Hv, Av / 128, (NMENT / 64) * (Av / 128) };       // 64
        GJob ju = { mention, Wu, p_mu, nullptr, nullptr, nullptr, nullptr,
                    Hv, Hv, Av, 0, Hv, Av / 128, (NMENT / 64) * (Av / 128) };       // 64
        GJob js = { Wr, RM, p_swT, nullptr, nullptr, nullptr, nullptr,
                    RMSv, RMSv, Rv, 0, RMSv, Rv / 128, (Hv / 64) * (Rv / 128) };    // 128
        gemm3_kernel<<<jv.nblk + ju.nblk + js.nblk, 256, SMEM_BYTES>>>(jv, ju, js);
    }

    // 3. gate logits [2048]; d vector
    gate_kernel<<<NMENT / 8, 256>>>(bv, bu, Wa);
    dvec_kernel<<<Hv / 8, 256>>>(Wo + Hv, Hv + RMSv);

    // 4. W2 = swT @ rmT^T   [1024(h), 512(m)], K=1024
    {
        GJob jw = { p_swT, p_rmT, p_W2, nullptr, nullptr, nullptr, nullptr,
                    Rv, Rv, RMSv, 0, Rv, RMSv / 128, (Hv / 64) * (RMSv / 128) };    // 64
        gemm3_kernel<<<jw.nblk, 256, SMEM_BYTES>>>(jw, Z, Z);
    }

    // 5. softmax over K + pool -> entity_reprs [1024, 1024]
    softmax_pool_kernel<<<NBE, 256>>>(mention, entities, masks);

    // 6. Wcomb[o,h] = Wo2 @ W2^T + Wo1[o,h] + d[o] br[h]   [1024, 1024], K=512
    {
        GJob jc = { Wo + Hv, p_W2, p_Wc, nullptr, Wo, p_d, br,
                    Hv + RMSv, RMSv, Hv, Hv + RMSv, RMSv, Hv / 128, (Hv / 64) * (Hv / 128) };  // 128
        gemm3_kernel<<<jc.nblk, 256, SMEM_BYTES>>>(jc, Z, Z);
    }

    // 7. out = ER @ Wcomb^T + bo   [1024, 1024], K=1024
    {
        GJob jf = { p_er, p_Wc, out, bo, nullptr, nullptr, nullptr,
                    Hv, Hv, Hv, 0, Hv, Hv / 128, (NBE / 64) * (Hv / 128) };         // 128
        gemm3_kernel<<<jf.nblk, 256, SMEM_BYTES>>>(jf, Z, Z);
    }
}

// round 13
// speedup vs baseline: 1.0049x; 1.0049x over previous
#include <cuda_runtime.h>
#include <cuda_bf16.h>
#include <math.h>
#include <stdint.h>

// ---------------- problem constants ----------------
#define Bv   8
#define Mv   256
#define Ev   128
#define Kv   16
#define Hv   1024
#define Av   256
#define Rv   1024
#define RMSv 512
#define NEGV (-1e25f)
#define MROWS (Bv*Ev*Kv)   // 16384
#define NBE   (Bv*Ev)      // 1024
#define NMENT (Bv*Mv)      // 2048 distinct mention rows

// ---------------- scratch (static device globals) ----------------
__device__ float g_mv[NMENT * Av];     // per-mention V projection
__device__ float g_mu[NMENT * Av];     // per-mention U projection
__device__ float g_gate[NMENT];        // per-mention gate logit
__device__ float g_er[NBE * Hv];       // pooled entity reprs
__device__ float g_swT[Hv * Rv];       // swT[h,r] = (Wr @ RM^T)[h,r]
__device__ float g_W2[Hv * RMSv];      // W2[h,m]  = (swT @ RM)[h,m]
__device__ float g_Wc[Hv * Hv];        // Wcomb[o,h] = Wo1 + Wo2@W2^T + d br^T
__device__ float g_rmT[RMSv * Rv];     // RM^T
__device__ float g_q[RMSv];            // colsum(RM)
__device__ float g_d[Hv];              // d[o] = Wo2[o,:].q

// ---------------- helpers ----------------
__device__ __forceinline__ uint32_t smem_u32(const void* p) {
    uint32_t a;
    asm("{ .reg .u64 t; cvta.to.shared.u64 t, %1; cvt.u32.u64 %0, t; }" : "=r"(a) : "l"(p));
    return a;
}
__device__ __forceinline__ uint32_t pack_bf16x2(float x, float y) {
    __nv_bfloat162 h = __floats2bfloat162_rn(x, y);
    return *(uint32_t*)&h;
}
__device__ __forceinline__ float bf16_round(float x) {
    return __bfloat162float(__float2bfloat16(x));
}

#define LDMATRIX_X4(r0, r1, r2, r3, addr) \
    asm volatile("ldmatrix.sync.aligned.m8n8.x4.shared.b16 {%0,%1,%2,%3}, [%4];" \
        : "=r"(r0), "=r"(r1), "=r"(r2), "=r"(r3) : "r"(addr))

#define MMA_BF16(c, a, b) \
    asm volatile("mma.sync.aligned.m16n8k16.row.col.f32.bf16.bf16.f32 " \
        "{%0,%1,%2,%3}, {%4,%5,%6,%7}, {%8,%9}, {%0,%1,%2,%3};" \
        : "+f"((c)[0]), "+f"((c)[1]), "+f"((c)[2]), "+f"((c)[3]) \
        : "r"((a)[0]), "r"((a)[1]), "r"((a)[2]), "r"((a)[3]), "r"((b)[0]), "r"((b)[1]))

// ---------------------------------------------------------------------------
// Multi-job NT GEMM, bf16x3 fp32 emulation, double-buffered smem,
// register-staged prefetch. C[M,N] = A[M,K] * B[N,K]^T (+bias[n]) (+addM) (+u v^T)
// BM=64, BN=128, BK=32, 256 threads (8 warps, 2x4). 1-D grid, job dispatch.
// ---------------------------------------------------------------------------
struct GJob {
    const float *A, *B;
    float *C;
    const float *bias;   // per-col, nullable
    const float *addM;   // addend matrix [row,col], nullable
    const float *r1u;    // rank-1 u[row], nullable (with r1v)
    const float *r1v;    // rank-1 v[col]
    int lda, ldb, ldc, ldadd, Kdim, nb, nblk;
};

#define SMEM_BYTES 61440
// per-buffer: A = 2 splits x 64 x 40, B = 2 splits x 128 x 40 (bf16)
#define SA_OFF(buf, sp, row) ((buf)*15360 + (sp)*2560 + (row)*40)
#define SB_OFF(buf, sp, row) ((buf)*15360 + 5120 + (sp)*5120 + (row)*40)

__global__ __launch_bounds__(256)
void gemm3_kernel(GJob j0, GJob j1, GJob j2)
{
    extern __shared__ __nv_bfloat16 smw[];
    constexpr int AIT = 2, BIT = 4, NT = 4;

    int bid = blockIdx.x;
    GJob j = j0;
    if (bid >= j0.nblk) {
        bid -= j0.nblk; j = j1;
        if (bid >= j1.nblk) { bid -= j1.nblk; j = j2; }
    }

    const int tid  = threadIdx.x;
    const int wid  = tid >> 5;
    const int lane = tid & 31;
    const int warp_m = wid & 1;
    const int warp_n = wid >> 1;
    const int m0 = (bid / j.nb) * 64;
    const int n0 = (bid % j.nb) * 128;

    const int srow = tid >> 3;            // 0..31
    const int sc4  = (tid & 7) << 2;      // 0,4,...,28

    const float* aBase = j.A + (size_t)(m0 + srow) * j.lda + sc4;
    const float* bBase = j.B + (size_t)(n0 + srow) * j.ldb + sc4;

    float4 ra[AIT], rb[BIT];
    #pragma unroll
    for (int i = 0; i < AIT; i++) ra[i] = *(const float4*)(aBase + (size_t)(i * 32) * j.lda);
    #pragma unroll
    for (int i = 0; i < BIT; i++) rb[i] = *(const float4*)(bBase + (size_t)(i * 32) * j.ldb);

    float cfr[2][NT][4];
    #pragma unroll
    for (int mt = 0; mt < 2; mt++)
        #pragma unroll
        for (int nt = 0; nt < NT; nt++)
            #pragma unroll
            for (int q = 0; q < 4; q++) cfr[mt][nt][q] = 0.0f;

    const int nCh = j.Kdim >> 5;
    for (int ch = 0; ch < nCh; ch++) {
        const int buf = ch & 1;
        // ---- convert staged regs -> smem (hi/lo bf16) ----
        #pragma unroll
        for (int i = 0; i < AIT; i++) {
            float4 v = ra[i];
            int row = i * 32 + srow;
            float hx = bf16_round(v.x), hy = bf16_round(v.y);
            float hz = bf16_round(v.z), hw = bf16_round(v.w);
            uint2 hi, lo;
            hi.x = pack_bf16x2(hx, hy);         hi.y = pack_bf16x2(hz, hw);
            lo.x = pack_bf16x2(v.x-hx, v.y-hy); lo.y = pack_bf16x2(v.z-hz, v.w-hw);
            *(uint2*)(smw + SA_OFF(buf, 0, row) + sc4) = hi;
            *(uint2*)(smw + SA_OFF(buf, 1, row) + sc4) = lo;
        }
        #pragma unroll
        for (int i = 0; i < BIT; i++) {
            float4 v = rb[i];
            int row = i * 32 + srow;
            float hx = bf16_round(v.x), hy = bf16_round(v.y);
            float hz = bf16_round(v.z), hw = bf16_round(v.w);
            uint2 hi, lo;
            hi.x = pack_bf16x2(hx, hy);         hi.y = pack_bf16x2(hz, hw);
            lo.x = pack_bf16x2(v.x-hx, v.y-hy); lo.y = pack_bf16x2(v.z-hz, v.w-hw);
            *(uint2*)(smw + SB_OFF(buf, 0, row) + sc4) = hi;
            *(uint2*)(smw + SB_OFF(buf, 1, row) + sc4) = lo;
        }
        __syncthreads();   // single barrier per chunk (double buffered)

        // ---- prefetch next chunk (overlaps MMA) ----
        if (ch + 1 < nCh) {
            int koff = (ch + 1) << 5;
            #pragma unroll
            for (int i = 0; i < AIT; i++) ra[i] = *(const float4*)(aBase + (size_t)(i * 32) * j.lda + koff);
            #pragma unroll
            for (int i = 0; i < BIT; i++) rb[i] = *(const float4*)(bBase + (size_t)(i * 32) * j.ldb + koff);
        }

        // ---- MMA: per k-step 3 split products, fragment reuse ----
        #pragma unroll
        for (int ks = 0; ks < 2; ks++) {
            const int acol = ks * 16 + ((lane >> 4) << 3);
            const int arow = warp_m * 32 + (lane & 15);
            const int bcol = ks * 16 + (((lane >> 3) & 1) << 3);
            const int brow = warp_n * 32 + (lane & 7) + ((lane >> 4) << 3);

            uint32_t afH[2][4];
            #pragma unroll
            for (int mt = 0; mt < 2; mt++)
                LDMATRIX_X4(afH[mt][0], afH[mt][1], afH[mt][2], afH[mt][3],
                            smem_u32(smw + SA_OFF(buf, 0, arow + mt * 16) + acol));
            uint32_t bfH[NT][2];
            #pragma unroll
            for (int np = 0; np < NT / 2; np++) {
                uint32_t r0, r1, r2, r3;
                LDMATRIX_X4(r0, r1, r2, r3,
                            smem_u32(smw + SB_OFF(buf, 0, brow + np * 16) + bcol));
                bfH[np*2][0] = r0;   bfH[np*2][1] = r1;
                bfH[np*2+1][0] = r2; bfH[np*2+1][1] = r3;
            }
            #pragma unroll
            for (int mt = 0; mt < 2; mt++)
                #pragma unroll
                for (int nt = 0; nt < NT; nt++) MMA_BF16(cfr[mt][nt], afH[mt], bfH[nt]);
            {
                uint32_t bfL[NT][2];
                #pragma unroll
                for (int np = 0; np < NT / 2; np++) {
                    uint32_t r0, r1, r2, r3;
                    LDMATRIX_X4(r0, r1, r2, r3,
                                smem_u32(smw + SB_OFF(buf, 1, brow + np * 16) + bcol));
                    bfL[np*2][0] = r0;   bfL[np*2][1] = r1;
                    bfL[np*2+1][0] = r2; bfL[np*2+1][1] = r3;
                }
                #pragma unroll
                for (int mt = 0; mt < 2; mt++)
                    #pragma unroll
                    for (int nt = 0; nt < NT; nt++) MMA_BF16(cfr[mt][nt], afH[mt], bfL[nt]);
            }
            {
                uint32_t afL[2][4];
                #pragma unroll
                for (int mt = 0; mt < 2; mt++)
                    LDMATRIX_X4(afL[mt][0], afL[mt][1], afL[mt][2], afL[mt][3],
                                smem_u32(smw + SA_OFF(buf, 1, arow + mt * 16) + acol));
                #pragma unroll
                for (int mt = 0; mt < 2; mt++)
                    #pragma unroll
                    for (int nt = 0; nt < NT; nt++) MMA_BF16(cfr[mt][nt], afL[mt], bfH[nt]);
            }
        }
        __syncthreads();   // protect buf reuse two chunks later
    }

    // ---- epilogue ----
    const int g = lane >> 2;
    const int t = lane & 3;
    #pragma unroll
    for (int mt = 0; mt < 2; mt++) {
        #pragma unroll
        for (int nt = 0; nt < NT; nt++) {
            int row = m0 + warp_m * 32 + mt * 16 + g;
            int col = n0 + warp_n * 32 + nt * 8 + t * 2;
            float v0 = cfr[mt][nt][0], v1 = cfr[mt][nt][1];
            float v2 = cfr[mt][nt][2], v3 = cfr[mt][nt][3];
            if (j.addM) {
                const float* q0 = &j.addM[(size_t)row * j.ldadd + col];
                const float* q1 = &j.addM[(size_t)(row + 8) * j.ldadd + col];
                v0 += q0[0]; v1 += q0[1]; v2 += q1[0]; v3 += q1[1];
            }
            if (j.r1u) {
                float u0 = j.r1u[row], u1 = j.r1u[row + 8];
                float w0 = j.r1v[col], w1 = j.r1v[col + 1];
                v0 += u0 * w0; v1 += u0 * w1; v2 += u1 * w0; v3 += u1 * w1;
            }
            if (j.bias) {
                float b0 = j.bias[col], b1 = j.bias[col + 1];
                v0 += b0; v1 += b1; v2 += b0; v3 += b1;
            }
            float* p0 = &j.C[(size_t)row * j.ldc + col];
            float* p1 = &j.C[(size_t)(row + 8) * j.ldc + col];
            *(float2*)p0 = make_float2(v0, v1);
            *(float2*)p1 = make_float2(v2, v3);
        }
    }
}

// ---------------- per-mention gate: tanh(mv+bv)*sigmoid(mu+bu) . Wa ----------------
__global__ __launch_bounds__(256)
void gate_kernel(const float* __restrict__ bv, const float* __restrict__ bu,
                 const float* __restrict__ Wa)
{
    int r = blockIdx.x * 8 + (threadIdx.x >> 5);
    int lane = threadIdx.x & 31;
    const float* pv = g_mv + (size_t)r * Av;
    const float* pu = g_mu + (size_t)r * Av;
    float s = 0.0f;
    #pragma unroll
    for (int jj = 0; jj < 8; jj++) {
        int a = lane + jj * 32;
        float tv = tanhf(pv[a] + bv[a]);
        float su = 1.0f / (1.0f + expf(-(pu[a] + bu[a])));
        s += tv * su * Wa[a];
    }
    #pragma unroll
    for (int o = 16; o > 0; o >>= 1) s += __shfl_xor_sync(0xFFFFFFFF, s, o);
    if (lane == 0) g_gate[r] = s;
}

// ---------------- masked softmax over K + weighted pooling ----------------
__global__ __launch_bounds__(256)
void softmax_pool_kernel(const float* __restrict__ mention,
                         const int*   __restrict__ entities,
                         const int*   __restrict__ masks)
{
    const int be = blockIdx.x;
    const int b  = be / Ev;
    __shared__ float w[Kv];
    __shared__ int   idx[Kv];
    const int tid = threadIdx.x;
    if (tid < Kv) {
        int r = be * Kv + tid;
        int m = entities[r];
        idx[tid] = m;
        w[tid]   = masks[r] ? g_gate[b * Mv + m] : NEGV;
    }
    __syncthreads();
    if (tid == 0) {
        float mx = w[0];
        #pragma unroll
        for (int k = 1; k < Kv; k++) mx = fmaxf(mx, w[k]);
        float s = 0.0f;
        #pragma unroll
        for (int k = 0; k < Kv; k++) { float e = expf(w[k] - mx); w[k] = e; s += e; }
        float inv = 1.0f / s;
        #pragma unroll
        for (int k = 0; k < Kv; k++) w[k] *= inv;
    }
    __syncthreads();
    float ww[Kv]; int ii[Kv];
    #pragma unroll
    for (int k = 0; k < Kv; k++) { ww[k] = w[k]; ii[k] = idx[k]; }
    const float* base = mention + (size_t)b * Mv * Hv;
    for (int h = tid; h < Hv; h += 256) {
        float acc = 0.0f;
        #pragma unroll
        for (int k = 0; k < Kv; k++)
            acc += ww[k] * base[(size_t)ii[k] * Hv + h];
        g_er[(size_t)be * Hv + h] = acc;
    }
}

// ---------------- transpose relation_memory: g_rmT[m,r] = RM[r,m] ----------------
__global__ void transpose_rm_kernel(const float* __restrict__ RM)
{
    __shared__ float tile[32][33];
    int tx = threadIdx.x, ty = threadIdx.y;
    int n0 = blockIdx.x * 32, k0 = blockIdx.y * 32;
    #pragma unroll
    for (int jj = 0; jj < 32; jj += 8)
        tile[ty + jj][tx] = RM[(size_t)(k0 + ty + jj) * RMSv + n0 + tx];
    __syncthreads();
    #pragma unroll
    for (int jj = 0; jj < 32; jj += 8)
        g_rmT[(size_t)(n0 + ty + jj) * Rv + k0 + tx] = tile[tx][ty + jj];
}

// ---------------- q = colsum(RM) ----------------
__global__ __launch_bounds__(128)
void colsum_kernel(const float* __restrict__ RM)
{
    int col = blockIdx.x * 128 + threadIdx.x;   // 4 blocks x 128 = 512
    float s = 0.0f;
    for (int r = 0; r < Rv; r++) s += RM[(size_t)r * RMSv + col];
    g_q[col] = s;
}

// ---------------- d[o] = Wo2[o,:] . q ----------------
__global__ __launch_bounds__(256)
void dvec_kernel(const float* __restrict__ Wo2, int ldw)
{
    int o = blockIdx.x * 8 + (threadIdx.x >> 5);
    int lane = threadIdx.x & 31;
    const float* row = Wo2 + (size_t)o * ldw;
    float s = 0.0f;
    #pragma unroll
    for (int jj = 0; jj < RMSv / 32; jj++) s += row[lane + jj * 32] * g_q[lane + jj * 32];
    #pragma unroll
    for (int off = 16; off > 0; off >>= 1) s += __shfl_xor_sync(0xFFFFFFFF, s, off);
    if (lane == 0) g_d[o] = s;
}

// ---------------- launch ----------------
extern "C" void kernel_launch(void* const* d_in, const int* in_sizes, int n_in,
                              void* d_out, int out_size)
{
    const float* mention  = (const float*)d_in[0];
    const int*   entities = (const int*)  d_in[1];
    const int*   masks    = (const int*)  d_in[2];
    const float* RM       = (const float*)d_in[3];
    const float* Wv       = (const float*)d_in[4];
    const float* bv       = (const float*)d_in[5];
    const float* Wu       = (const float*)d_in[6];
    const float* bu       = (const float*)d_in[7];
    const float* Wa       = (const float*)d_in[8];
    // d_in[9] = ba : additive constant inside softmax -> no-op
    const float* Wr       = (const float*)d_in[10];
    const float* br       = (const float*)d_in[11];
    const float* Wo       = (const float*)d_in[12];
    const float* bo       = (const float*)d_in[13];
    float* out = (float*)d_out;

    cudaFuncSetAttribute(gemm3_kernel, cudaFuncAttributeMaxDynamicSharedMemorySize, SMEM_BYTES);

    float *p_mv, *p_mu, *p_er, *p_swT, *p_W2, *p_Wc, *p_rmT, *p_d;
    cudaGetSymbolAddress((void**)&p_mv,  g_mv);
    cudaGetSymbolAddress((void**)&p_mu,  g_mu);
    cudaGetSymbolAddress((void**)&p_er,  g_er);
    cudaGetSymbolAddress((void**)&p_swT, g_swT);
    cudaGetSymbolAddress((void**)&p_W2,  g_W2);
    cudaGetSymbolAddress((void**)&p_Wc,  g_Wc);
    cudaGetSymbolAddress((void**)&p_rmT, g_rmT);
    cudaGetSymbolAddress((void**)&p_d,   g_d);

    GJob Z = {};   // zero job (nblk = 0)

    // 1. transpose RM -> rmT [512, 1024]; q = colsum(RM)
    { dim3 g(RMSv / 32, Rv / 32), b(32, 8); transpose_rm_kernel<<<g, b>>>(RM); }
    colsum_kernel<<<RMSv / 128, 128>>>(RM);

    // 2. fused launch: mv = mention@Wv^T, mu = mention@Wu^T, swT = Wr@RM^T
    {
        GJob jv = { mention, Wv, p_mv, nullptr, nullptr, nullptr, nullptr,
                    Hv, Hv, Av, 0, Hv, Av / 128, (NMENT / 64) * (Av / 128) };       // 64
        GJob ju = { mention, Wu, p_mu, nullptr, nullptr, nullptr, nullptr,
                    Hv, Hv, Av, 0, Hv, Av / 128, (NMENT / 64) * (Av / 128) };       // 64
        GJob js = { Wr, RM, p_swT, nullptr, nullptr, nullptr, nullptr,
                    RMSv, RMSv, Rv, 0, RMSv, Rv / 128, (Hv / 64) * (Rv / 128) };    // 128
        gemm3_kernel<<<jv.nblk + ju.nblk + js.nblk, 256, SMEM_BYTES>>>(jv, ju, js);
    }

    // 3. gate logits [2048]; d vector
    gate_kernel<<<NMENT / 8, 256>>>(bv, bu, Wa);
    dvec_kernel<<<Hv / 8, 256>>>(Wo + Hv, Hv + RMSv);

    // 4. W2 = swT @ rmT^T   [1024(h), 512(m)], K=1024
    {
        GJob jw = { p_swT, p_rmT, p_W2, nullptr, nullptr, nullptr, nullptr,
                    Rv, Rv, RMSv, 0, Rv, RMSv / 128, (Hv / 64) * (RMSv / 128) };    // 64
        gemm3_kernel<<<jw.nblk, 256, SMEM_BYTES>>>(jw, Z, Z);
    }

    // 5. softmax over K + pool -> entity_reprs [1024, 1024]
    softmax_pool_kernel<<<NBE, 256>>>(mention, entities, masks);

    // 6. Wcomb[o,h] = Wo2 @ W2^T + Wo1[o,h] + d[o] br[h]   [1024, 1024], K=512
    {
        GJob jc = { Wo + Hv, p_W2, p_Wc, nullptr, Wo, p_d, br,
                    Hv + RMSv, RMSv, Hv, Hv + RMSv, RMSv, Hv / 128, (Hv / 64) * (Hv / 128) };  // 128
        gemm3_kernel<<<jc.nblk, 256, SMEM_BYTES>>>(jc, Z, Z);
    }

    // 7. out = ER @ Wcomb^T + bo   [1024, 1024], K=1024
    {
        GJob jf = { p_er, p_Wc, out, bo, nullptr, nullptr, nullptr,
                    Hv, Hv, Hv, 0, Hv, Hv / 128, (NBE / 64) * (Hv / 128) };         // 128
        gemm3_kernel<<<jf.nblk, 256, SMEM_BYTES>>>(jf, Z, Z);
    }
}

// round 14
// speedup vs baseline: 1.0190x; 1.0140x over previous
#include <cuda_runtime.h>
#include <cuda_bf16.h>
#include <math.h>
#include <stdint.h>

// ---------------- problem constants ----------------
#define Bv   8
#define Mv   256
#define Ev   128
#define Kv   16
#define Hv   1024
#define Av   256
#define Rv   1024
#define RMSv 512
#define NEGV (-1e25f)
#define MROWS (Bv*Ev*Kv)   // 16384
#define NBE   (Bv*Ev)      // 1024
#define NMENT (Bv*Mv)      // 2048 distinct mention rows

// ---------------- scratch (static device globals) ----------------
__device__ float g_mv[NMENT * Av];     // per-mention V projection
__device__ float g_mu[NMENT * Av];     // per-mention U projection
__device__ float g_gate[NMENT];        // per-mention gate logit
__device__ float g_er[NBE * Hv];       // pooled entity reprs
__device__ float g_swT[Hv * Rv];       // swT[h,r] = (Wr @ RM^T)[h,r]
__device__ float g_W2[Hv * RMSv];      // W2[h,m]  = (swT @ RM)[h,m]
__device__ float g_Wc[Hv * Hv];        // Wcomb[o,h] = Wo1 + Wo2@W2^T + d br^T
__device__ float g_rmT[RMSv * Rv];     // RM^T
__device__ float g_q[RMSv];            // colsum(RM)
__device__ float g_d[Hv];              // d[o] = Wo2[o,:].q

// ---------------- helpers ----------------
__device__ __forceinline__ uint32_t smem_u32(const void* p) {
    uint32_t a;
    asm("{ .reg .u64 t; cvta.to.shared.u64 t, %1; cvt.u32.u64 %0, t; }" : "=r"(a) : "l"(p));
    return a;
}
__device__ __forceinline__ uint32_t pack_bf16x2(float x, float y) {
    __nv_bfloat162 h = __floats2bfloat162_rn(x, y);
    return *(uint32_t*)&h;
}
__device__ __forceinline__ float bf16_round(float x) {
    return __bfloat162float(__float2bfloat16(x));
}

#define LDMATRIX_X4(r0, r1, r2, r3, addr) \
    asm volatile("ldmatrix.sync.aligned.m8n8.x4.shared.b16 {%0,%1,%2,%3}, [%4];" \
        : "=r"(r0), "=r"(r1), "=r"(r2), "=r"(r3) : "r"(addr))

#define MMA_BF16(c, a, b) \
    asm volatile("mma.sync.aligned.m16n8k16.row.col.f32.bf16.bf16.f32 " \
        "{%0,%1,%2,%3}, {%4,%5,%6,%7}, {%8,%9}, {%0,%1,%2,%3};" \
        : "+f"((c)[0]), "+f"((c)[1]), "+f"((c)[2]), "+f"((c)[3]) \
        : "r"((a)[0]), "r"((a)[1]), "r"((a)[2]), "r"((a)[3]), "r"((b)[0]), "r"((b)[1]))

// ---------------------------------------------------------------------------
// Multi-job NT GEMM, bf16x3 fp32 emulation, double-buffered smem,
// register-staged prefetch. C[M,N] = A[M,K] * B[N,K]^T (+bias[n]) (+addM) (+u v^T)
// BM=64, BN=128, BK=32, 256 threads (8 warps, 2x4). 1-D grid, job dispatch.
// ---------------------------------------------------------------------------
struct GJob {
    const float *A, *B;
    float *C;
    const float *bias;   // per-col, nullable
    const float *addM;   // addend matrix [row,col], nullable
    const float *r1u;    // rank-1 u[row], nullable (with r1v)
    const float *r1v;    // rank-1 v[col]
    int lda, ldb, ldc, ldadd, Kdim, nb, nblk;
};

#define SMEM_BYTES 61440
// per-buffer: A = 2 splits x 64 x 40, B = 2 splits x 128 x 40 (bf16)
#define SA_OFF(buf, sp, row) ((buf)*15360 + (sp)*2560 + (row)*40)
#define SB_OFF(buf, sp, row) ((buf)*15360 + 5120 + (sp)*5120 + (row)*40)

__global__ __launch_bounds__(256)
void gemm3_kernel(GJob j0, GJob j1, GJob j2)
{
    extern __shared__ __nv_bfloat16 smw[];
    constexpr int AIT = 2, BIT = 4, NT = 4;

    int bid = blockIdx.x;
    GJob j = j0;
    if (bid >= j0.nblk) {
        bid -= j0.nblk; j = j1;
        if (bid >= j1.nblk) { bid -= j1.nblk; j = j2; }
    }

    const int tid  = threadIdx.x;
    const int wid  = tid >> 5;
    const int lane = tid & 31;
    const int warp_m = wid & 1;
    const int warp_n = wid >> 1;
    const int m0 = (bid / j.nb) * 64;
    const int n0 = (bid % j.nb) * 128;

    const int srow = tid >> 3;            // 0..31
    const int sc4  = (tid & 7) << 2;      // 0,4,...,28

    const float* aBase = j.A + (size_t)(m0 + srow) * j.lda + sc4;
    const float* bBase = j.B + (size_t)(n0 + srow) * j.ldb + sc4;

    float4 ra[AIT], rb[BIT];
    #pragma unroll
    for (int i = 0; i < AIT; i++) ra[i] = *(const float4*)(aBase + (size_t)(i * 32) * j.lda);
    #pragma unroll
    for (int i = 0; i < BIT; i++) rb[i] = *(const float4*)(bBase + (size_t)(i * 32) * j.ldb);

    float cfr[2][NT][4];
    #pragma unroll
    for (int mt = 0; mt < 2; mt++)
        #pragma unroll
        for (int nt = 0; nt < NT; nt++)
            #pragma unroll
            for (int q = 0; q < 4; q++) cfr[mt][nt][q] = 0.0f;

    const int nCh = j.Kdim >> 5;
    for (int ch = 0; ch < nCh; ch++) {
        const int buf = ch & 1;
        // ---- convert staged regs -> smem (hi/lo bf16) ----
        #pragma unroll
        for (int i = 0; i < AIT; i++) {
            float4 v = ra[i];
            int row = i * 32 + srow;
            float hx = bf16_round(v.x), hy = bf16_round(v.y);
            float hz = bf16_round(v.z), hw = bf16_round(v.w);
            uint2 hi, lo;
            hi.x = pack_bf16x2(hx, hy);         hi.y = pack_bf16x2(hz, hw);
            lo.x = pack_bf16x2(v.x-hx, v.y-hy); lo.y = pack_bf16x2(v.z-hz, v.w-hw);
            *(uint2*)(smw + SA_OFF(buf, 0, row) + sc4) = hi;
            *(uint2*)(smw + SA_OFF(buf, 1, row) + sc4) = lo;
        }
        #pragma unroll
        for (int i = 0; i < BIT; i++) {
            float4 v = rb[i];
            int row = i * 32 + srow;
            float hx = bf16_round(v.x), hy = bf16_round(v.y);
            float hz = bf16_round(v.z), hw = bf16_round(v.w);
            uint2 hi, lo;
            hi.x = pack_bf16x2(hx, hy);         hi.y = pack_bf16x2(hz, hw);
            lo.x = pack_bf16x2(v.x-hx, v.y-hy); lo.y = pack_bf16x2(v.z-hz, v.w-hw);
            *(uint2*)(smw + SB_OFF(buf, 0, row) + sc4) = hi;
            *(uint2*)(smw + SB_OFF(buf, 1, row) + sc4) = lo;
        }
        __syncthreads();   // single barrier per chunk (double buffered)

        // ---- prefetch next chunk (overlaps MMA) ----
        if (ch + 1 < nCh) {
            int koff = (ch + 1) << 5;
            #pragma unroll
            for (int i = 0; i < AIT; i++) ra[i] = *(const float4*)(aBase + (size_t)(i * 32) * j.lda + koff);
            #pragma unroll
            for (int i = 0; i < BIT; i++) rb[i] = *(const float4*)(bBase + (size_t)(i * 32) * j.ldb + koff);
        }

        // ---- MMA: per k-step 3 split products, fragment reuse ----
        #pragma unroll
        for (int ks = 0; ks < 2; ks++) {
            const int acol = ks * 16 + ((lane >> 4) << 3);
            const int arow = warp_m * 32 + (lane & 15);
            const int bcol = ks * 16 + (((lane >> 3) & 1) << 3);
            const int brow = warp_n * 32 + (lane & 7) + ((lane >> 4) << 3);

            uint32_t afH[2][4];
            #pragma unroll
            for (int mt = 0; mt < 2; mt++)
                LDMATRIX_X4(afH[mt][0], afH[mt][1], afH[mt][2], afH[mt][3],
                            smem_u32(smw + SA_OFF(buf, 0, arow + mt * 16) + acol));
            uint32_t bfH[NT][2];
            #pragma unroll
            for (int np = 0; np < NT / 2; np++) {
                uint32_t r0, r1, r2, r3;
                LDMATRIX_X4(r0, r1, r2, r3,
                            smem_u32(smw + SB_OFF(buf, 0, brow + np * 16) + bcol));
                bfH[np*2][0] = r0;   bfH[np*2][1] = r1;
                bfH[np*2+1][0] = r2; bfH[np*2+1][1] = r3;
            }
            #pragma unroll
            for (int mt = 0; mt < 2; mt++)
                #pragma unroll
                for (int nt = 0; nt < NT; nt++) MMA_BF16(cfr[mt][nt], afH[mt], bfH[nt]);
            {
                uint32_t bfL[NT][2];
                #pragma unroll
                for (int np = 0; np < NT / 2; np++) {
                    uint32_t r0, r1, r2, r3;
                    LDMATRIX_X4(r0, r1, r2, r3,
                                smem_u32(smw + SB_OFF(buf, 1, brow + np * 16) + bcol));
                    bfL[np*2][0] = r0;   bfL[np*2][1] = r1;
                    bfL[np*2+1][0] = r2; bfL[np*2+1][1] = r3;
                }
                #pragma unroll
                for (int mt = 0; mt < 2; mt++)
                    #pragma unroll
                    for (int nt = 0; nt < NT; nt++) MMA_BF16(cfr[mt][nt], afH[mt], bfL[nt]);
            }
            {
                uint32_t afL[2][4];
                #pragma unroll
                for (int mt = 0; mt < 2; mt++)
                    LDMATRIX_X4(afL[mt][0], afL[mt][1], afL[mt][2], afL[mt][3],
                                smem_u32(smw + SA_OFF(buf, 1, arow + mt * 16) + acol));
                #pragma unroll
                for (int mt = 0; mt < 2; mt++)
                    #pragma unroll
                    for (int nt = 0; nt < NT; nt++) MMA_BF16(cfr[mt][nt], afL[mt], bfH[nt]);
            }
        }
        __syncthreads();   // protect buf reuse two chunks later
    }

    // ---- epilogue ----
    const int g = lane >> 2;
    const int t = lane & 3;
    #pragma unroll
    for (int mt = 0; mt < 2; mt++) {
        #pragma unroll
        for (int nt = 0; nt < NT; nt++) {
            int row = m0 + warp_m * 32 + mt * 16 + g;
            int col = n0 + warp_n * 32 + nt * 8 + t * 2;
            float v0 = cfr[mt][nt][0], v1 = cfr[mt][nt][1];
            float v2 = cfr[mt][nt][2], v3 = cfr[mt][nt][3];
            if (j.addM) {
                const float* q0 = &j.addM[(size_t)row * j.ldadd + col];
                const float* q1 = &j.addM[(size_t)(row + 8) * j.ldadd + col];
                v0 += q0[0]; v1 += q0[1]; v2 += q1[0]; v3 += q1[1];
            }
            if (j.r1u) {
                float u0 = j.r1u[row], u1 = j.r1u[row + 8];
                float w0 = j.r1v[col], w1 = j.r1v[col + 1];
                v0 += u0 * w0; v1 += u0 * w1; v2 += u1 * w0; v3 += u1 * w1;
            }
            if (j.bias) {
                float b0 = j.bias[col], b1 = j.bias[col + 1];
                v0 += b0; v1 += b1; v2 += b0; v3 += b1;
            }
            float* p0 = &j.C[(size_t)row * j.ldc + col];
            float* p1 = &j.C[(size_t)(row + 8) * j.ldc + col];
            *(float2*)p0 = make_float2(v0, v1);
            *(float2*)p1 = make_float2(v2, v3);
        }
    }
}

// ---------------- per-mention gate: tanh(mv+bv)*sigmoid(mu+bu) . Wa ----------------
__global__ __launch_bounds__(256)
void gate_kernel(const float* __restrict__ bv, const float* __restrict__ bu,
                 const float* __restrict__ Wa)
{
    int r = blockIdx.x * 8 + (threadIdx.x >> 5);
    int lane = threadIdx.x & 31;
    const float* pv = g_mv + (size_t)r * Av;
    const float* pu = g_mu + (size_t)r * Av;
    float s = 0.0f;
    #pragma unroll
    for (int jj = 0; jj < 8; jj++) {
        int a = lane + jj * 32;
        float tv = tanhf(pv[a] + bv[a]);
        float su = 1.0f / (1.0f + expf(-(pu[a] + bu[a])));
        s += tv * su * Wa[a];
    }
    #pragma unroll
    for (int o = 16; o > 0; o >>= 1) s += __shfl_xor_sync(0xFFFFFFFF, s, o);
    if (lane == 0) g_gate[r] = s;
}

// ---------------- masked softmax over K + weighted pooling ----------------
__global__ __launch_bounds__(256)
void softmax_pool_kernel(const float* __restrict__ mention,
                         const int*   __restrict__ entities,
                         const int*   __restrict__ masks)
{
    const int be = blockIdx.x;
    const int b  = be / Ev;
    __shared__ float w[Kv];
    __shared__ int   idx[Kv];
    const int tid = threadIdx.x;
    if (tid < Kv) {
        int r = be * Kv + tid;
        int m = entities[r];
        idx[tid] = m;
        w[tid]   = masks[r] ? g_gate[b * Mv + m] : NEGV;
    }
    __syncthreads();
    if (tid == 0) {
        float mx = w[0];
        #pragma unroll
        for (int k = 1; k < Kv; k++) mx = fmaxf(mx, w[k]);
        float s = 0.0f;
        #pragma unroll
        for (int k = 0; k < Kv; k++) { float e = expf(w[k] - mx); w[k] = e; s += e; }
        float inv = 1.0f / s;
        #pragma unroll
        for (int k = 0; k < Kv; k++) w[k] *= inv;
    }
    __syncthreads();
    float ww[Kv]; int ii[Kv];
    #pragma unroll
    for (int k = 0; k < Kv; k++) { ww[k] = w[k]; ii[k] = idx[k]; }
    const float* base = mention + (size_t)b * Mv * Hv;
    for (int h = tid; h < Hv; h += 256) {
        float acc = 0.0f;
        #pragma unroll
        for (int k = 0; k < Kv; k++)
            acc += ww[k] * base[(size_t)ii[k] * Hv + h];
        g_er[(size_t)be * Hv + h] = acc;
    }
}

// ---------------- transpose relation_memory: g_rmT[m,r] = RM[r,m] ----------------
__global__ void transpose_rm_kernel(const float* __restrict__ RM)
{
    __shared__ float tile[32][33];
    int tx = threadIdx.x, ty = threadIdx.y;
    int n0 = blockIdx.x * 32, k0 = blockIdx.y * 32;
    #pragma unroll
    for (int jj = 0; jj < 32; jj += 8)
        tile[ty + jj][tx] = RM[(size_t)(k0 + ty + jj) * RMSv + n0 + tx];
    __syncthreads();
    #pragma unroll
    for (int jj = 0; jj < 32; jj += 8)
        g_rmT[(size_t)(n0 + ty + jj) * Rv + k0 + tx] = tile[tx][ty + jj];
}

// ---------------- q = colsum(RM) ----------------
__global__ __launch_bounds__(128)
void colsum_kernel(const float* __restrict__ RM)
{
    int col = blockIdx.x * 128 + threadIdx.x;   // 4 blocks x 128 = 512
    float s = 0.0f;
    for (int r = 0; r < Rv; r++) s += RM[(size_t)r * RMSv + col];
    g_q[col] = s;
}

// ---------------- d[o] = Wo2[o,:] . q ----------------
__global__ __launch_bounds__(256)
void dvec_kernel(const float* __restrict__ Wo2, int ldw)
{
    int o = blockIdx.x * 8 + (threadIdx.x >> 5);
    int lane = threadIdx.x & 31;
    const float* row = Wo2 + (size_t)o * ldw;
    float s = 0.0f;
    #pragma unroll
    for (int jj = 0; jj < RMSv / 32; jj++) s += row[lane + jj * 32] * g_q[lane + jj * 32];
    #pragma unroll
    for (int off = 16; off > 0; off >>= 1) s += __shfl_xor_sync(0xFFFFFFFF, s, off);
    if (lane == 0) g_d[o] = s;
}

// ---------------- launch ----------------
extern "C" void kernel_launch(void* const* d_in, const int* in_sizes, int n_in,
                              void* d_out, int out_size)
{
    const float* mention  = (const float*)d_in[0];
    const int*   entities = (const int*)  d_in[1];
    const int*   masks    = (const int*)  d_in[2];
    const float* RM       = (const float*)d_in[3];
    const float* Wv       = (const float*)d_in[4];
    const float* bv       = (const float*)d_in[5];
    const float* Wu       = (const float*)d_in[6];
    const float* bu       = (const float*)d_in[7];
    const float* Wa       = (const float*)d_in[8];
    // d_in[9] = ba : additive constant inside softmax -> no-op
    const float* Wr       = (const float*)d_in[10];
    const float* br       = (const float*)d_in[11];
    const float* Wo       = (const float*)d_in[12];
    const float* bo       = (const float*)d_in[13];
    float* out = (float*)d_out;

    cudaFuncSetAttribute(gemm3_kernel, cudaFuncAttributeMaxDynamicSharedMemorySize, SMEM_BYTES);

    float *p_mv, *p_mu, *p_er, *p_swT, *p_W2, *p_Wc, *p_rmT, *p_d;
    cudaGetSymbolAddress((void**)&p_mv,  g_mv);
    cudaGetSymbolAddress((void**)&p_mu,  g_mu);
    cudaGetSymbolAddress((void**)&p_er,  g_er);
    cudaGetSymbolAddress((void**)&p_swT, g_swT);
    cudaGetSymbolAddress((void**)&p_W2,  g_W2);
    cudaGetSymbolAddress((void**)&p_Wc,  g_Wc);
    cudaGetSymbolAddress((void**)&p_rmT, g_rmT);
    cudaGetSymbolAddress((void**)&p_d,   g_d);

    GJob Z = {};   // zero job (nblk = 0)

    // 1. transpose RM -> rmT [512, 1024]; q = colsum(RM)
    { dim3 g(RMSv / 32, Rv / 32), b(32, 8); transpose_rm_kernel<<<g, b>>>(RM); }
    colsum_kernel<<<RMSv / 128, 128>>>(RM);

    // 2. fused launch: mv = mention@Wv^T, mu = mention@Wu^T, swT = Wr@RM^T
    {
        GJob jv = { mention, Wv, p_mv, nullptr, nullptr, nullptr, nullptr,
                    Hv, Hv, Av, 0, Hv, Av / 128, (NMENT / 64) * (Av / 128) };       // 64
        GJob ju = { mention, Wu, p_mu, nullptr, nullptr, nullptr, nullptr,
                    Hv, Hv, Av, 0, Hv, Av / 128, (NMENT / 64) * (Av / 128) };       // 64
        GJob js = { Wr, RM, p_swT, nullptr, nullptr, nullptr, nullptr,
                    RMSv, RMSv, Rv, 0, RMSv, Rv / 128, (Hv / 64) * (Rv / 128) };    // 128
        gemm3_kernel<<<jv.nblk + ju.nblk + js.nblk, 256, SMEM_BYTES>>>(jv, ju, js);
    }

    // 3. gate logits [2048]; d vector
    gate_kernel<<<NMENT / 8, 256>>>(bv, bu, Wa);
    dvec_kernel<<<Hv / 8, 256>>>(Wo + Hv, Hv + RMSv);

    // 4. W2 = swT @ rmT^T   [1024(h), 512(m)], K=1024
    {
        GJob jw = { p_swT, p_rmT, p_W2, nullptr, nullptr, nullptr, nullptr,
                    Rv, Rv, RMSv, 0, Rv, RMSv / 128, (Hv / 64) * (RMSv / 128) };    // 64
        gemm3_kernel<<<jw.nblk, 256, SMEM_BYTES>>>(jw, Z, Z);
    }

    // 5. softmax over K + pool -> entity_reprs [1024, 1024]
    softmax_pool_kernel<<<NBE, 256>>>(mention, entities, masks);

    // 6. Wcomb[o,h] = Wo2 @ W2^T + Wo1[o,h] + d[o] br[h]   [1024, 1024], K=512
    {
        GJob jc = { Wo + Hv, p_W2, p_Wc, nullptr, Wo, p_d, br,
                    Hv + RMSv, RMSv, Hv, Hv + RMSv, RMSv, Hv / 128, (Hv / 64) * (Hv / 128) };  // 128
        gemm3_kernel<<<jc.nblk, 256, SMEM_BYTES>>>(jc, Z, Z);
    }

    // 7. out = ER @ Wcomb^T + bo   [1024, 1024], K=1024
    {
        GJob jf = { p_er, p_Wc, out, bo, nullptr, nullptr, nullptr,
                    Hv, Hv, Hv, 0, Hv, Hv / 128, (NBE / 64) * (Hv / 128) };         // 128
        gemm3_kernel<<<jf.nblk, 256, SMEM_BYTES>>>(jf, Z, Z);
    }
}